// round 15
// baseline (speedup 1.0000x reference)
#include <cuda_runtime.h>
#include <cuda_fp16.h>
#include <math.h>
#include <stdint.h>

// ---------------- problem constants ----------------
#define B_  32
#define T_  2048
#define H_  1024
#define NROWS (B_ * T_)          // 65536
#define HALF_ROWS (NROWS / 2)    // 32768
#define BHALF (B_ / 2)           // 16 batches per half

// GEMM tiling (fp16): BM 128 x BN 128, K-chunk 64, 2 CTAs/SM
#define BM 128
#define BN 128
#define BKH 64
#define NCTILE (H_ / BN)         // 8
#define CHUNKS (H_ / BKH)        // 16

// dynamic smem per CTA: A0[16K] A1[16K] B0[16K] B1[16K] = 64KB
#define OFF_A0 0
#define OFF_A1 16384
#define OFF_B0 32768
#define OFF_B1 49152
#define DSMEM_BYTES 65536

// ctx pass tiling
#define CTC 8
#define CTS (T_ / CTC)           // 256

// ---------------- device scratch ----------------
__device__ __half g_Ah[(size_t)NROWS * H_];     // gru as fp16 (128 MB)
__device__ __half g_Wh[H_ * H_];                // W^T as fp16
__device__ float  g_partials[NROWS * NCTILE];
__device__ float  g_ctxPartial[B_ * CTC * H_];

// ---------------- PTX helpers (baseline ISA only) ----------------
__device__ __forceinline__ uint32_t smem_u32(const void* p) {
    uint32_t a;
    asm("{ .reg .u64 t; cvta.to.shared.u64 t, %1; cvt.u32.u64 %0, t; }" : "=r"(a) : "l"(p));
    return a;
}
__device__ __forceinline__ void ldsm4(uint32_t& r0, uint32_t& r1, uint32_t& r2,
                                      uint32_t& r3, uint32_t addr) {
    asm volatile("ldmatrix.sync.aligned.m8n8.x4.shared.b16 {%0,%1,%2,%3}, [%4];"
                 : "=r"(r0), "=r"(r1), "=r"(r2), "=r"(r3) : "r"(addr));
}
__device__ __forceinline__ void mma_f16(float* d, const uint32_t* a,
                                        uint32_t b0, uint32_t b1) {
    asm volatile("mma.sync.aligned.m16n8k16.row.col.f32.f16.f16.f32 "
                 "{%0,%1,%2,%3}, {%4,%5,%6,%7}, {%8,%9}, {%0,%1,%2,%3};"
                 : "+f"(d[0]), "+f"(d[1]), "+f"(d[2]), "+f"(d[3])
                 : "r"(a[0]), "r"(a[1]), "r"(a[2]), "r"(a[3]), "r"(b0), "r"(b1));
}
#define CP_ASYNC16(dst, src) \
    asm volatile("cp.async.cg.shared.global [%0], [%1], 16;" :: "r"(dst), "l"(src))
#define CP_COMMIT() asm volatile("cp.async.commit_group;" ::: "memory")
#define CP_WAIT0()  asm volatile("cp.async.wait_group 0;" ::: "memory")

// ---------------- kernel 0a: transpose W -> fp16 ----------------
__global__ __launch_bounds__(256) void transpose_w_kernel(const float* __restrict__ W,
                                                          __half* __restrict__ Wh) {
    __shared__ float t[32][33];
    const int tx = threadIdx.x, ty = threadIdx.y;        // (32, 8)
    const int bx = blockIdx.x * 32, by = blockIdx.y * 32;
#pragma unroll
    for (int i = 0; i < 32; i += 8)
        t[ty + i][tx] = W[(size_t)(by + ty + i) * H_ + bx + tx];
    __syncthreads();
#pragma unroll
    for (int i = 0; i < 32; i += 8)
        Wh[(size_t)(bx + ty + i) * H_ + by + tx] = __float2half_rn(t[tx][ty + i]);
}

// ---------------- kernel 0b: gru fp32 -> fp16 (128-thr, 2xfloat4 ILP) -----
__global__ __launch_bounds__(128) void convert_gru_kernel(const float4* __restrict__ in,
                                                          uint2* __restrict__ out,
                                                          int n4) {
    int i = blockIdx.x * 256 + threadIdx.x;
    const int stride = gridDim.x * 256;
    for (; i + 128 < n4; i += stride) {
        float4 v0 = in[i];
        float4 v1 = in[i + 128];
        __half2 a0 = __floats2half2_rn(v0.x, v0.y);
        __half2 b0 = __floats2half2_rn(v0.z, v0.w);
        __half2 a1 = __floats2half2_rn(v1.x, v1.y);
        __half2 b1 = __floats2half2_rn(v1.z, v1.w);
        uint2 o0, o1;
        o0.x = *reinterpret_cast<uint32_t*>(&a0);
        o0.y = *reinterpret_cast<uint32_t*>(&b0);
        o1.x = *reinterpret_cast<uint32_t*>(&a1);
        o1.y = *reinterpret_cast<uint32_t*>(&b1);
        out[i]       = o0;
        out[i + 128] = o1;
    }
    if (i < n4) {
        float4 v = in[i];
        __half2 lo = __floats2half2_rn(v.x, v.y);
        __half2 hi = __floats2half2_rn(v.z, v.w);
        uint2 o;
        o.x = *reinterpret_cast<uint32_t*>(&lo);
        o.y = *reinterpret_cast<uint32_t*>(&hi);
        out[i] = o;
    }
}

// ---------------- kernel A: fp16 mma.sync GEMM + tanh·c partial reduce ----
// grid (NCTILE=8, rows/128), block 256 (8 warps: 2M x 4N, warp tile 64x32)
// launch_bounds(256,2): 2 CTAs/SM -> independent barrier domains overlap.
__global__ __launch_bounds__(256, 2) void gemm_mma_kernel(
    const __half* __restrict__ Ah,   // [NROWS, H] fp16
    const __half* __restrict__ Wh,   // [H, H] = W^T fp16
    const float* __restrict__ cvec,  // [H]
    float* __restrict__ partials,    // [NROWS, NCTILE]
    int rowOff)
{
    extern __shared__ char dsm[];
    __shared__ float cs[BN];
    __shared__ float red[BM][4];

    const uint32_t sbase = smem_u32(dsm);
    const int tid  = threadIdx.x;
    const int lane = tid & 31;
    const int wid  = tid >> 5;
    const int warpM = wid & 1;       // 2 -> row groups of 64
    const int warpN = wid >> 1;      // 4 -> col groups of 32
    const int colBase = blockIdx.x * BN;
    const int rowBase = rowOff + blockIdx.y * BM;

    if (tid < BN) cs[tid] = cvec[colBase + tid];

    // loader: 256 threads, 8 x 16B segs per 128B row -> 32 rows per pass
    const int ldRow = tid >> 3;               // 0..31
    const int ldSeg = tid & 7;                // 0..7
    const int sseg  = ldSeg ^ (ldRow & 7);    // SW128-swizzled seg (constant)
    const uint32_t dstBase = (uint32_t)(ldRow * 128 + sseg * 16);

    const __half* Ag = Ah + (size_t)(rowBase + ldRow) * H_ + ldSeg * 8;
    const __half* Bg = Wh + (size_t)(colBase + ldRow) * H_ + ldSeg * 8;

    float acc[4][4][4];
#pragma unroll
    for (int i = 0; i < 4; i++)
#pragma unroll
        for (int j = 0; j < 4; j++)
#pragma unroll
            for (int k = 0; k < 4; k++) acc[i][j][k] = 0.f;

    const uint32_t offA[2] = {OFF_A0, OFF_A1};
    const uint32_t offB[2] = {OFF_B0, OFF_B1};

    // ---- preload chunk 0 ----
#pragma unroll
    for (int p = 0; p < 4; p++)           // A: 128 rows
        CP_ASYNC16(sbase + OFF_A0 + dstBase + p * 4096, Ag + (size_t)(p * 32) * H_);
#pragma unroll
    for (int p = 0; p < 4; p++)           // B: 128 rows
        CP_ASYNC16(sbase + OFF_B0 + dstBase + p * 4096, Bg + (size_t)(p * 32) * H_);
    CP_COMMIT();
    CP_WAIT0();
    __syncthreads();

    int buf = 0;
    for (int ck = 0; ck < CHUNKS; ck++) {
        const bool more = (ck + 1 < CHUNKS);
        if (more) {
            const int kk = (ck + 1) * BKH;
#pragma unroll
            for (int p = 0; p < 4; p++)
                CP_ASYNC16(sbase + offA[buf ^ 1] + dstBase + p * 4096,
                           Ag + kk + (size_t)(p * 32) * H_);
#pragma unroll
            for (int p = 0; p < 4; p++)
                CP_ASYNC16(sbase + offB[buf ^ 1] + dstBase + p * 4096,
                           Bg + kk + (size_t)(p * 32) * H_);
            CP_COMMIT();
        }

        // ---- compute on buf: 4 k-steps of K=16 halves (32B each) ----
        const uint32_t aBuf = sbase + offA[buf];
        const uint32_t bBuf = sbase + offB[buf];
#pragma unroll
        for (int s = 0; s < 4; s++) {
            uint32_t afr[4][4];
#pragma unroll
            for (int mt = 0; mt < 4; mt++) {
                const int r = warpM * 64 + mt * 16 + (lane & 15);
                const int seg16 = 2 * s + (lane >> 4);
                ldsm4(afr[mt][0], afr[mt][1], afr[mt][2], afr[mt][3],
                      aBuf + r * 128 + ((seg16 ^ (r & 7)) << 4));
            }
#pragma unroll
            for (int q = 0; q < 2; q++) {
                uint32_t bq0, bq1, bq2, bq3;
                const int rn = warpN * 32 + q * 16 + ((lane >> 4) << 3) + (lane & 7);
                const int seg16 = 2 * s + ((lane >> 3) & 1);
                ldsm4(bq0, bq1, bq2, bq3,
                      bBuf + rn * 128 + ((seg16 ^ (rn & 7)) << 4));
#pragma unroll
                for (int mt = 0; mt < 4; mt++) {
                    mma_f16(acc[mt][2 * q],     afr[mt], bq0, bq1);
                    mma_f16(acc[mt][2 * q + 1], afr[mt], bq2, bq3);
                }
            }
        }

        if (more) CP_WAIT0();
        __syncthreads();
        buf ^= 1;
    }

    // ---- epilogue: sum_n tanh(D) * c over this CTA's 128 cols ----
#pragma unroll
    for (int mt = 0; mt < 4; mt++) {
        float slo = 0.f, shi = 0.f;
#pragma unroll
        for (int nt = 0; nt < 4; nt++) {
            const int n = warpN * 32 + nt * 8 + (lane & 3) * 2;
            const float c0 = cs[n], c1 = cs[n + 1];
            slo += tanhf(acc[mt][nt][0]) * c0 + tanhf(acc[mt][nt][1]) * c1;
            shi += tanhf(acc[mt][nt][2]) * c0 + tanhf(acc[mt][nt][3]) * c1;
        }
        slo += __shfl_xor_sync(0xffffffffu, slo, 1);
        slo += __shfl_xor_sync(0xffffffffu, slo, 2);
        shi += __shfl_xor_sync(0xffffffffu, shi, 1);
        shi += __shfl_xor_sync(0xffffffffu, shi, 2);
        if ((lane & 3) == 0) {
            const int r0 = warpM * 64 + mt * 16 + (lane >> 2);
            red[r0][warpN]     = slo;
            red[r0 + 8][warpN] = shi;
        }
    }
    __syncthreads();
    if (tid < BM)
        partials[(size_t)(rowBase + tid) * NCTILE + blockIdx.x] =
            (red[tid][0] + red[tid][1]) + (red[tid][2] + red[tid][3]);
}

// ---------------- kernel C: logits reduce + softmax over T (batch group) --
__global__ __launch_bounds__(1024) void softmax_kernel(
    const float* __restrict__ partials, float* __restrict__ out, int bOff)
{
    __shared__ float lg[T_];
    __shared__ float redv[32];
    __shared__ float sBcast;
    const int b = bOff + blockIdx.x, tid = threadIdx.x;

    for (int t = tid; t < T_; t += 1024) {
        const float* p = &partials[(size_t)(b * T_ + t) * NCTILE];
        float s = 0.f;
#pragma unroll
        for (int q = 0; q < NCTILE; q++) s += p[q];
        lg[t] = s;
    }
    __syncthreads();

    float m = fmaxf(lg[tid], lg[tid + 1024]);
#pragma unroll
    for (int o = 16; o > 0; o >>= 1) m = fmaxf(m, __shfl_xor_sync(0xffffffffu, m, o));
    if ((tid & 31) == 0) redv[tid >> 5] = m;
    __syncthreads();
    if (tid < 32) {
        float v = redv[tid];
#pragma unroll
        for (int o = 16; o > 0; o >>= 1) v = fmaxf(v, __shfl_xor_sync(0xffffffffu, v, o));
        if (tid == 0) sBcast = v;
    }
    __syncthreads();
    const float M = sBcast;

    const float e0 = expf(lg[tid] - M);
    const float e1 = expf(lg[tid + 1024] - M);
    float z = e0 + e1;
#pragma unroll
    for (int o = 16; o > 0; o >>= 1) z += __shfl_xor_sync(0xffffffffu, z, o);
    if ((tid & 31) == 0) redv[tid >> 5] = z;
    __syncthreads();
    if (tid < 32) {
        float v = redv[tid];
#pragma unroll
        for (int o = 16; o > 0; o >>= 1) v += __shfl_xor_sync(0xffffffffu, v, o);
        if (tid == 0) sBcast = v;
    }
    __syncthreads();
    const float invZ = 1.0f / sBcast;

    float* attn = out + (size_t)B_ * H_ + (size_t)b * T_;
    attn[tid]        = e0 * invZ;
    attn[tid + 1024] = e1 * invZ;
}

// ---------------- kernel D1: context partials (128-thr) ----------------
__global__ __launch_bounds__(128) void ctx_partial_kernel(
    const __half* __restrict__ Ah, const float* __restrict__ out,
    float* __restrict__ ctxp, int bOff)
{
    __shared__ float at[CTS];
    const int hc = blockIdx.x, tc = blockIdx.y, b = bOff + blockIdx.z;
    const int h2 = hc * 128 + threadIdx.x;      // half2 index (0..511)

    const float* attn = out + (size_t)B_ * H_ + (size_t)b * T_ + tc * CTS;
    for (int i = threadIdx.x; i < CTS; i += 128) at[i] = attn[i];
    __syncthreads();

    const __half2* g = (const __half2*)(Ah + ((size_t)b * T_ + tc * CTS) * H_) + h2;
    float ax = 0.f, ay = 0.f;
#pragma unroll 8
    for (int t = 0; t < CTS; t++) {
        float2 v = __half22float2(g[(size_t)t * (H_ / 2)]);
        const float w = at[t];
        ax += w * v.x;
        ay += w * v.y;
    }
    float2* dst = (float2*)(ctxp + ((size_t)(b * CTC + tc) * H_)) + h2;
    *dst = make_float2(ax, ay);
}

// ---------------- kernel D2: reduce context partials (batch group) --------
__global__ __launch_bounds__(256) void ctx_reduce_kernel(
    const float* __restrict__ ctxp, float* __restrict__ out, int bOff)
{
    const int b = bOff + blockIdx.x;
    for (int h = threadIdx.x; h < H_; h += 256) {
        float s = 0.f;
#pragma unroll
        for (int q = 0; q < CTC; q++) s += ctxp[(b * CTC + q) * H_ + h];
        out[(size_t)b * H_ + h] = s;
    }
}

// ---------------- launch ----------------
extern "C" void kernel_launch(void* const* d_in, const int* in_sizes, int n_in,
                              void* d_out, int out_size) {
    const float* gru  = (const float*)d_in[0];
    const float* W    = (const float*)d_in[1];
    const float* cvec = (const float*)d_in[2];
    float* out = (float*)d_out;

    __half *Ah = nullptr, *Wh = nullptr;
    float *partials = nullptr, *ctxp = nullptr;
    cudaGetSymbolAddress((void**)&Ah, g_Ah);
    cudaGetSymbolAddress((void**)&Wh, g_Wh);
    cudaGetSymbolAddress((void**)&partials, g_partials);
    cudaGetSymbolAddress((void**)&ctxp, g_ctxPartial);

    static cudaStream_t s2 = nullptr, s3 = nullptr;
    static cudaEvent_t evFork = nullptr, evW = nullptr, evConv1 = nullptr,
                       evG0 = nullptr, evEpi0 = nullptr;
    if (!s2) {
        cudaStreamCreateWithFlags(&s2, cudaStreamNonBlocking);
        cudaStreamCreateWithFlags(&s3, cudaStreamNonBlocking);
        cudaEventCreateWithFlags(&evFork, cudaEventDisableTiming);
        cudaEventCreateWithFlags(&evW, cudaEventDisableTiming);
        cudaEventCreateWithFlags(&evConv1, cudaEventDisableTiming);
        cudaEventCreateWithFlags(&evG0, cudaEventDisableTiming);
        cudaEventCreateWithFlags(&evEpi0, cudaEventDisableTiming);
        cudaFuncSetAttribute(gemm_mma_kernel,
                             cudaFuncAttributeMaxDynamicSharedMemorySize, DSMEM_BYTES);
    }

    const int n4_half = HALF_ROWS * H_ / 4;

    // s0: conv half0.  s2 (forked): transpose, then conv half1.
    cudaEventRecord(evFork, 0);
    cudaStreamWaitEvent(s2, evFork, 0);
    transpose_w_kernel<<<dim3(32, 32), dim3(32, 8), 0, s2>>>(W, Wh);
    cudaEventRecord(evW, s2);
    convert_gru_kernel<<<8192, 128, 0, s2>>>(
        (const float4*)(gru + (size_t)HALF_ROWS * H_),
        (uint2*)(Ah + (size_t)HALF_ROWS * H_), n4_half);
    cudaEventRecord(evConv1, s2);

    convert_gru_kernel<<<8192, 128>>>((const float4*)gru, (uint2*)Ah, n4_half);

    // s0: gemm half0 (needs Wh)
    cudaStreamWaitEvent(0, evW, 0);
    gemm_mma_kernel<<<dim3(NCTILE, HALF_ROWS / BM), 256, DSMEM_BYTES>>>(
        Ah, Wh, cvec, partials, 0);
    cudaEventRecord(evG0, 0);

    // s3: epilogue for half0 batches (overlaps gemm1 tail)
    cudaStreamWaitEvent(s3, evG0, 0);
    softmax_kernel<<<BHALF, 1024, 0, s3>>>(partials, out, 0);
    ctx_partial_kernel<<<dim3(4, CTC, BHALF), 128, 0, s3>>>(Ah, out, ctxp, 0);
    ctx_reduce_kernel<<<BHALF, 256, 0, s3>>>(ctxp, out, 0);
    cudaEventRecord(evEpi0, s3);

    // s0: gemm half1 (needs conv half1)
    cudaStreamWaitEvent(0, evConv1, 0);
    gemm_mma_kernel<<<dim3(NCTILE, HALF_ROWS / BM), 256, DSMEM_BYTES>>>(
        Ah, Wh, cvec, partials, HALF_ROWS);

    // s0: epilogue for half1 batches
    softmax_kernel<<<BHALF, 1024>>>(partials, out, BHALF);
    ctx_partial_kernel<<<dim3(4, CTC, BHALF), 128>>>(Ah, out, ctxp, BHALF);
    ctx_reduce_kernel<<<BHALF, 256>>>(ctxp, out, BHALF);

    // join s3 back into s0
    cudaStreamWaitEvent(0, evEpi0, 0);
}

// round 16
// speedup vs baseline: 1.0124x; 1.0124x over previous
#include <cuda_runtime.h>
#include <cuda_fp16.h>
#include <math.h>
#include <stdint.h>

// ---------------- problem constants ----------------
#define B_  32
#define T_  2048
#define H_  1024
#define NROWS (B_ * T_)          // 65536
#define HALF_ROWS (NROWS / 2)    // 32768
#define BHALF (B_ / 2)           // 16 batches per half

// GEMM tiling (fp16). Outer K-chunk = 128 halves, stored as 2 sub-tiles of 64.
#define BM 256
#define BN 128
#define NCTILE (H_ / BN)         // 8
#define CHUNKS2 (H_ / 128)       // 8 outer chunks

// dynamic smem: A buf0[64K] A buf1[64K] B buf0[32K] B buf1[32K] = 192KB
#define DSMEM_BYTES 196608

// ctx pass tiling
#define CTC 8
#define CTS (T_ / CTC)           // 256

// ---------------- device scratch ----------------
__device__ __half g_Ah[(size_t)NROWS * H_];     // gru as fp16 (128 MB)
__device__ __half g_Wh[H_ * H_];                // W^T as fp16
__device__ float  g_partials[NROWS * NCTILE];
__device__ float  g_ctxPartial[B_ * CTC * H_];

// ---------------- PTX helpers (baseline ISA only) ----------------
__device__ __forceinline__ uint32_t smem_u32(const void* p) {
    uint32_t a;
    asm("{ .reg .u64 t; cvta.to.shared.u64 t, %1; cvt.u32.u64 %0, t; }" : "=r"(a) : "l"(p));
    return a;
}
__device__ __forceinline__ void ldsm4(uint32_t& r0, uint32_t& r1, uint32_t& r2,
                                      uint32_t& r3, uint32_t addr) {
    asm volatile("ldmatrix.sync.aligned.m8n8.x4.shared.b16 {%0,%1,%2,%3}, [%4];"
                 : "=r"(r0), "=r"(r1), "=r"(r2), "=r"(r3) : "r"(addr));
}
__device__ __forceinline__ void mma_f16(float* d, const uint32_t* a,
                                        uint32_t b0, uint32_t b1) {
    asm volatile("mma.sync.aligned.m16n8k16.row.col.f32.f16.f16.f32 "
                 "{%0,%1,%2,%3}, {%4,%5,%6,%7}, {%8,%9}, {%0,%1,%2,%3};"
                 : "+f"(d[0]), "+f"(d[1]), "+f"(d[2]), "+f"(d[3])
                 : "r"(a[0]), "r"(a[1]), "r"(a[2]), "r"(a[3]), "r"(b0), "r"(b1));
}
#define CP_ASYNC16(dst, src) \
    asm volatile("cp.async.cg.shared.global [%0], [%1], 16;" :: "r"(dst), "l"(src))
#define CP_COMMIT() asm volatile("cp.async.commit_group;" ::: "memory")
#define CP_WAIT0()  asm volatile("cp.async.wait_group 0;" ::: "memory")

// ---------------- kernel 0a: transpose W -> fp16 ----------------
__global__ __launch_bounds__(256) void transpose_w_kernel(const float* __restrict__ W,
                                                          __half* __restrict__ Wh) {
    __shared__ float t[32][33];
    const int tx = threadIdx.x, ty = threadIdx.y;        // (32, 8)
    const int bx = blockIdx.x * 32, by = blockIdx.y * 32;
#pragma unroll
    for (int i = 0; i < 32; i += 8)
        t[ty + i][tx] = W[(size_t)(by + ty + i) * H_ + bx + tx];
    __syncthreads();
#pragma unroll
    for (int i = 0; i < 32; i += 8)
        Wh[(size_t)(bx + ty + i) * H_ + by + tx] = __float2half_rn(t[tx][ty + i]);
}

// ---------------- kernel 0b: gru fp32 -> fp16 (128-thr, 2xfloat4 ILP) -----
__global__ __launch_bounds__(128) void convert_gru_kernel(const float4* __restrict__ in,
                                                          uint2* __restrict__ out,
                                                          int n4) {
    int i = blockIdx.x * 256 + threadIdx.x;
    const int stride = gridDim.x * 256;
    for (; i + 128 < n4; i += stride) {
        float4 v0 = in[i];
        float4 v1 = in[i + 128];
        __half2 a0 = __floats2half2_rn(v0.x, v0.y);
        __half2 b0 = __floats2half2_rn(v0.z, v0.w);
        __half2 a1 = __floats2half2_rn(v1.x, v1.y);
        __half2 b1 = __floats2half2_rn(v1.z, v1.w);
        uint2 o0, o1;
        o0.x = *reinterpret_cast<uint32_t*>(&a0);
        o0.y = *reinterpret_cast<uint32_t*>(&b0);
        o1.x = *reinterpret_cast<uint32_t*>(&a1);
        o1.y = *reinterpret_cast<uint32_t*>(&b1);
        out[i]       = o0;
        out[i + 128] = o1;
    }
    if (i < n4) {
        float4 v = in[i];
        __half2 lo = __floats2half2_rn(v.x, v.y);
        __half2 hi = __floats2half2_rn(v.z, v.w);
        uint2 o;
        o.x = *reinterpret_cast<uint32_t*>(&lo);
        o.y = *reinterpret_cast<uint32_t*>(&hi);
        out[i] = o;
    }
}

// ---------------- kernel A: fp16 mma.sync GEMM + tanh·c partial reduce ----
// grid (NCTILE=8, 128), block 512 (16 warps: 4x4, warp tile 64x32)
// __maxnreg__(120): direct cap (NOT launch_bounds - R12 showed that overshoots
// to 96+spills). 120*512 = 61440 -> frees 4096 regs/SM so one 128-thr aux
// block (conv / ctx_partial) can genuinely co-reside with the GEMM.
__global__ void __maxnreg__(120) gemm_mma_kernel(
    const __half* __restrict__ Ah,   // [NROWS, H] fp16
    const __half* __restrict__ Wh,   // [H, H] = W^T fp16
    const float* __restrict__ cvec,  // [H]
    float* __restrict__ partials,    // [NROWS, NCTILE]
    int rowOff)
{
    extern __shared__ char dsm[];
    __shared__ float cs[BN];
    __shared__ float red[BM][4];

    const uint32_t sbase = smem_u32(dsm);
    const int tid  = threadIdx.x;
    const int lane = tid & 31;
    const int wid  = tid >> 5;
    const int warpM = wid & 3;       // 4 -> row groups of 64
    const int warpN = wid >> 2;      // 4 -> col groups of 32
    const int colBase = blockIdx.x * BN;
    const int rowBase = rowOff + blockIdx.y * BM;

    if (tid < BN) cs[tid] = cvec[colBase + tid];

    // loader: 512 threads, 8 x 16B segs per 128B row -> 64 rows per pass
    const int ldRow = tid >> 3;               // 0..63
    const int ldSeg = tid & 7;                // 0..7
    const int sseg  = ldSeg ^ (ldRow & 7);    // SW128-swizzled seg (constant)
    const uint32_t dstBase = (uint32_t)(ldRow * 128 + sseg * 16);

    const __half* Ag = Ah + (size_t)(rowBase + ldRow) * H_ + ldSeg * 8;
    const __half* Bg = Wh + (size_t)(colBase + ldRow) * H_ + ldSeg * 8;

    float acc[4][4][4];
#pragma unroll
    for (int i = 0; i < 4; i++)
#pragma unroll
        for (int j = 0; j < 4; j++)
#pragma unroll
            for (int k = 0; k < 4; k++) acc[i][j][k] = 0.f;

    // buffers: A buf c at offA[c], holds 2 sub-tiles of 32KB; B 2 x 16KB
    const uint32_t offA[2] = {0u, 65536u};
    const uint32_t offB[2] = {131072u, 163840u};

    // ---- preload outer chunk 0 (both sub-tiles) ----
#pragma unroll
    for (int sub = 0; sub < 2; sub++) {
        const int kk = sub * 64;
#pragma unroll
        for (int p = 0; p < 4; p++)           // A: 256 rows
            CP_ASYNC16(sbase + offA[0] + sub * 32768u + dstBase + p * 8192,
                       Ag + kk + (size_t)(p * 64) * H_);
#pragma unroll
        for (int p = 0; p < 2; p++)           // B: 128 rows
            CP_ASYNC16(sbase + offB[0] + sub * 16384u + dstBase + p * 8192,
                       Bg + kk + (size_t)(p * 64) * H_);
    }
    CP_COMMIT();
    CP_WAIT0();
    __syncthreads();

    int buf = 0;
    for (int ck = 0; ck < CHUNKS2; ck++) {
        const bool more = (ck + 1 < CHUNKS2);
        if (more) {
            const int kkBase = (ck + 1) * 128;
#pragma unroll
            for (int sub = 0; sub < 2; sub++) {
                const int kk = kkBase + sub * 64;
#pragma unroll
                for (int p = 0; p < 4; p++)
                    CP_ASYNC16(sbase + offA[buf ^ 1] + sub * 32768u + dstBase + p * 8192,
                               Ag + kk + (size_t)(p * 64) * H_);
#pragma unroll
                for (int p = 0; p < 2; p++)
                    CP_ASYNC16(sbase + offB[buf ^ 1] + sub * 16384u + dstBase + p * 8192,
                               Bg + kk + (size_t)(p * 64) * H_);
            }
            CP_COMMIT();
        }

        // ---- compute: 2 sub-tiles x 4 k-steps of K=16 ----
#pragma unroll
        for (int sub = 0; sub < 2; sub++) {
            const uint32_t aBuf = sbase + offA[buf] + sub * 32768u;
            const uint32_t bBuf = sbase + offB[buf] + sub * 16384u;
#pragma unroll
            for (int s = 0; s < 4; s++) {
                uint32_t afr[4][4];
#pragma unroll
                for (int mt = 0; mt < 4; mt++) {
                    const int r = warpM * 64 + mt * 16 + (lane & 15);
                    const int seg16 = 2 * s + (lane >> 4);
                    ldsm4(afr[mt][0], afr[mt][1], afr[mt][2], afr[mt][3],
                          aBuf + r * 128 + ((seg16 ^ (r & 7)) << 4));
                }
#pragma unroll
                for (int q = 0; q < 2; q++) {
                    uint32_t bq0, bq1, bq2, bq3;
                    const int rn = warpN * 32 + q * 16 + ((lane >> 4) << 3) + (lane & 7);
                    const int seg16 = 2 * s + ((lane >> 3) & 1);
                    ldsm4(bq0, bq1, bq2, bq3,
                          bBuf + rn * 128 + ((seg16 ^ (rn & 7)) << 4));
#pragma unroll
                    for (int mt = 0; mt < 4; mt++) {
                        mma_f16(acc[mt][2 * q],     afr[mt], bq0, bq1);
                        mma_f16(acc[mt][2 * q + 1], afr[mt], bq2, bq3);
                    }
                }
            }
        }

        if (more) CP_WAIT0();
        __syncthreads();
        buf ^= 1;
    }

    // ---- epilogue: sum_n tanh(D) * c over this CTA's 128 cols ----
#pragma unroll
    for (int mt = 0; mt < 4; mt++) {
        float slo = 0.f, shi = 0.f;
#pragma unroll
        for (int nt = 0; nt < 4; nt++) {
            const int n = warpN * 32 + nt * 8 + (lane & 3) * 2;
            const float c0 = cs[n], c1 = cs[n + 1];
            slo += tanhf(acc[mt][nt][0]) * c0 + tanhf(acc[mt][nt][1]) * c1;
            shi += tanhf(acc[mt][nt][2]) * c0 + tanhf(acc[mt][nt][3]) * c1;
        }
        slo += __shfl_xor_sync(0xffffffffu, slo, 1);
        slo += __shfl_xor_sync(0xffffffffu, slo, 2);
        shi += __shfl_xor_sync(0xffffffffu, shi, 1);
        shi += __shfl_xor_sync(0xffffffffu, shi, 2);
        if ((lane & 3) == 0) {
            const int r0 = warpM * 64 + mt * 16 + (lane >> 2);
            red[r0][warpN]     = slo;
            red[r0 + 8][warpN] = shi;
        }
    }
    __syncthreads();
    if (tid < BM)
        partials[(size_t)(rowBase + tid) * NCTILE + blockIdx.x] =
            (red[tid][0] + red[tid][1]) + (red[tid][2] + red[tid][3]);
}

// ---------------- kernel C: logits reduce + softmax over T (batch group) --
__global__ __launch_bounds__(1024) void softmax_kernel(
    const float* __restrict__ partials, float* __restrict__ out, int bOff)
{
    __shared__ float lg[T_];
    __shared__ float redv[32];
    __shared__ float sBcast;
    const int b = bOff + blockIdx.x, tid = threadIdx.x;

    for (int t = tid; t < T_; t += 1024) {
        const float* p = &partials[(size_t)(b * T_ + t) * NCTILE];
        float s = 0.f;
#pragma unroll
        for (int q = 0; q < NCTILE; q++) s += p[q];
        lg[t] = s;
    }
    __syncthreads();

    float m = fmaxf(lg[tid], lg[tid + 1024]);
#pragma unroll
    for (int o = 16; o > 0; o >>= 1) m = fmaxf(m, __shfl_xor_sync(0xffffffffu, m, o));
    if ((tid & 31) == 0) redv[tid >> 5] = m;
    __syncthreads();
    if (tid < 32) {
        float v = redv[tid];
#pragma unroll
        for (int o = 16; o > 0; o >>= 1) v = fmaxf(v, __shfl_xor_sync(0xffffffffu, v, o));
        if (tid == 0) sBcast = v;
    }
    __syncthreads();
    const float M = sBcast;

    const float e0 = expf(lg[tid] - M);
    const float e1 = expf(lg[tid + 1024] - M);
    float z = e0 + e1;
#pragma unroll
    for (int o = 16; o > 0; o >>= 1) z += __shfl_xor_sync(0xffffffffu, z, o);
    if ((tid & 31) == 0) redv[tid >> 5] = z;
    __syncthreads();
    if (tid < 32) {
        float v = redv[tid];
#pragma unroll
        for (int o = 16; o > 0; o >>= 1) v += __shfl_xor_sync(0xffffffffu, v, o);
        if (tid == 0) sBcast = v;
    }
    __syncthreads();
    const float invZ = 1.0f / sBcast;

    float* attn = out + (size_t)B_ * H_ + (size_t)b * T_;
    attn[tid]        = e0 * invZ;
    attn[tid + 1024] = e1 * invZ;
}

// ---------------- kernel D1: context partials (128-thr, co-residable) -----
__global__ __launch_bounds__(128) void ctx_partial_kernel(
    const __half* __restrict__ Ah, const float* __restrict__ out,
    float* __restrict__ ctxp, int bOff)
{
    __shared__ float at[CTS];
    const int hc = blockIdx.x, tc = blockIdx.y, b = bOff + blockIdx.z;
    const int h2 = hc * 128 + threadIdx.x;      // half2 index (0..511)

    const float* attn = out + (size_t)B_ * H_ + (size_t)b * T_ + tc * CTS;
    for (int i = threadIdx.x; i < CTS; i += 128) at[i] = attn[i];
    __syncthreads();

    const __half2* g = (const __half2*)(Ah + ((size_t)b * T_ + tc * CTS) * H_) + h2;
    float ax = 0.f, ay = 0.f;
#pragma unroll 8
    for (int t = 0; t < CTS; t++) {
        float2 v = __half22float2(g[(size_t)t * (H_ / 2)]);
        const float w = at[t];
        ax += w * v.x;
        ay += w * v.y;
    }
    float2* dst = (float2*)(ctxp + ((size_t)(b * CTC + tc) * H_)) + h2;
    *dst = make_float2(ax, ay);
}

// ---------------- kernel D2: reduce context partials (batch group) --------
__global__ __launch_bounds__(256) void ctx_reduce_kernel(
    const float* __restrict__ ctxp, float* __restrict__ out, int bOff)
{
    const int b = bOff + blockIdx.x;
    for (int h = threadIdx.x; h < H_; h += 256) {
        float s = 0.f;
#pragma unroll
        for (int q = 0; q < CTC; q++) s += ctxp[(b * CTC + q) * H_ + h];
        out[(size_t)b * H_ + h] = s;
    }
}

// ---------------- launch ----------------
extern "C" void kernel_launch(void* const* d_in, const int* in_sizes, int n_in,
                              void* d_out, int out_size) {
    const float* gru  = (const float*)d_in[0];
    const float* W    = (const float*)d_in[1];
    const float* cvec = (const float*)d_in[2];
    float* out = (float*)d_out;

    __half *Ah = nullptr, *Wh = nullptr;
    float *partials = nullptr, *ctxp = nullptr;
    cudaGetSymbolAddress((void**)&Ah, g_Ah);
    cudaGetSymbolAddress((void**)&Wh, g_Wh);
    cudaGetSymbolAddress((void**)&partials, g_partials);
    cudaGetSymbolAddress((void**)&ctxp, g_ctxPartial);

    static cudaStream_t s2 = nullptr, s3 = nullptr;
    static cudaEvent_t evFork = nullptr, evW = nullptr, evConv1 = nullptr,
                       evG0 = nullptr, evEpi0 = nullptr;
    if (!s2) {
        cudaStreamCreateWithFlags(&s2, cudaStreamNonBlocking);
        cudaStreamCreateWithFlags(&s3, cudaStreamNonBlocking);
        cudaEventCreateWithFlags(&evFork, cudaEventDisableTiming);
        cudaEventCreateWithFlags(&evW, cudaEventDisableTiming);
        cudaEventCreateWithFlags(&evConv1, cudaEventDisableTiming);
        cudaEventCreateWithFlags(&evG0, cudaEventDisableTiming);
        cudaEventCreateWithFlags(&evEpi0, cudaEventDisableTiming);
        cudaFuncSetAttribute(gemm_mma_kernel,
                             cudaFuncAttributeMaxDynamicSharedMemorySize, DSMEM_BYTES);
    }

    const int n4_half = HALF_ROWS * H_ / 4;

    // s0: conv half0.  s2 (forked): transpose, then conv half1.
    cudaEventRecord(evFork, 0);
    cudaStreamWaitEvent(s2, evFork, 0);
    transpose_w_kernel<<<dim3(32, 32), dim3(32, 8), 0, s2>>>(W, Wh);
    cudaEventRecord(evW, s2);
    convert_gru_kernel<<<8192, 128, 0, s2>>>(
        (const float4*)(gru + (size_t)HALF_ROWS * H_),
        (uint2*)(Ah + (size_t)HALF_ROWS * H_), n4_half);
    cudaEventRecord(evConv1, s2);

    convert_gru_kernel<<<8192, 128>>>((const float4*)gru, (uint2*)Ah, n4_half);

    // s0: gemm half0 (needs Wh)
    cudaStreamWaitEvent(0, evW, 0);
    gemm_mma_kernel<<<dim3(NCTILE, HALF_ROWS / BM), 512, DSMEM_BYTES>>>(
        Ah, Wh, cvec, partials, 0);
    cudaEventRecord(evG0, 0);

    // s3: epilogue for half0 batches (co-resides with gemm1 if regs freed)
    cudaStreamWaitEvent(s3, evG0, 0);
    softmax_kernel<<<BHALF, 1024, 0, s3>>>(partials, out, 0);
    ctx_partial_kernel<<<dim3(4, CTC, BHALF), 128, 0, s3>>>(Ah, out, ctxp, 0);
    ctx_reduce_kernel<<<BHALF, 256, 0, s3>>>(ctxp, out, 0);
    cudaEventRecord(evEpi0, s3);

    // s0: gemm half1 (needs conv half1)
    cudaStreamWaitEvent(0, evConv1, 0);
    gemm_mma_kernel<<<dim3(NCTILE, HALF_ROWS / BM), 512, DSMEM_BYTES>>>(
        Ah, Wh, cvec, partials, HALF_ROWS);

    // s0: epilogue for half1 batches
    softmax_kernel<<<BHALF, 1024>>>(partials, out, BHALF);
    ctx_partial_kernel<<<dim3(4, CTC, BHALF), 128>>>(Ah, out, ctxp, BHALF);
    ctx_reduce_kernel<<<BHALF, 256>>>(ctxp, out, BHALF);

    // join s3 back into s0
    cudaStreamWaitEvent(0, evEpi0, 0);
}